// round 1
// baseline (speedup 1.0000x reference)
#include <cuda_runtime.h>
#include <math.h>

// Problem constants
#define BB 4
#define SS 2048
#define DD 1024
#define HH 16
#define DH 64
#define NT (BB*SS)          // 8192 tokens
#define SCALE_F 0.125f      // 64^-0.5

// Scratch (device globals: allocation-free rule)
__device__ float g_Q[(size_t)BB*HH*SS*DH];   // [B,H,S,Dh]
__device__ float g_K[(size_t)BB*HH*SS*DH];
__device__ float g_V[(size_t)BB*HH*SS*DH];
__device__ float g_O[(size_t)NT*DD];         // [B,S,D]

// ---------------------------------------------------------------------------
// 128x128x16 SGEMM, 256 threads, 8x8 per thread (split 4+4 rows/cols).
// amode: 0 -> A = Aparam, 1 -> A = g_O
// omode: 0/1/2 -> write [B,H,S,Dh] into g_Q/g_K/g_V ; 3 -> plain [M,N] to outp
// ---------------------------------------------------------------------------
__global__ __launch_bounds__(256) void gemm128(
    const float* __restrict__ Aparam, const float* __restrict__ W,
    const float* __restrict__ bias, float* __restrict__ outp,
    int amode, int omode)
{
    const int M = NT, N = DD, K = DD;
    const float* A = amode ? g_O : Aparam;
    float* out = (omode == 0) ? g_Q : (omode == 1) ? g_K : (omode == 2) ? g_V : outp;

    __shared__ float As[16][132];   // transposed A tile, padded
    __shared__ float Bs[16][128];

    const int bm = blockIdx.y * 128;
    const int bn = blockIdx.x * 128;
    const int tid = threadIdx.x;
    const int r0 = (tid >> 4) * 4;   // row base in tile
    const int c0 = (tid & 15) * 4;   // col base in tile

    float acc[8][8];
#pragma unroll
    for (int i = 0; i < 8; i++)
#pragma unroll
        for (int j = 0; j < 8; j++) acc[i][j] = 0.f;

    for (int k0 = 0; k0 < K; k0 += 16) {
#pragma unroll
        for (int t = 0; t < 2; t++) {
            int f4 = tid + t * 256;
            // A tile: 128 rows x 16 k -> 512 float4 (4 f4 per row)
            int ar = f4 >> 2, ac4 = f4 & 3;
            float4 va = *(const float4*)&A[(size_t)(bm + ar) * K + k0 + ac4 * 4];
            As[ac4 * 4 + 0][ar] = va.x;
            As[ac4 * 4 + 1][ar] = va.y;
            As[ac4 * 4 + 2][ar] = va.z;
            As[ac4 * 4 + 3][ar] = va.w;
            // B tile: 16 k x 128 cols -> 512 float4 (32 f4 per row)
            int br = f4 >> 5, bc4 = f4 & 31;
            *(float4*)&Bs[br][bc4 * 4] =
                *(const float4*)&W[(size_t)(k0 + br) * N + bn + bc4 * 4];
        }
        __syncthreads();
#pragma unroll
        for (int k = 0; k < 16; k++) {
            float ra[8], rb[8];
            *(float4*)&ra[0] = *(float4*)&As[k][r0];
            *(float4*)&ra[4] = *(float4*)&As[k][r0 + 64];
            *(float4*)&rb[0] = *(float4*)&Bs[k][c0];
            *(float4*)&rb[4] = *(float4*)&Bs[k][c0 + 64];
#pragma unroll
            for (int i = 0; i < 8; i++)
#pragma unroll
                for (int j = 0; j < 8; j++)
                    acc[i][j] += ra[i] * rb[j];
        }
        __syncthreads();
    }

    // Epilogue: bias add + layout
#pragma unroll
    for (int i = 0; i < 8; i++) {
        int gr = bm + r0 + ((i < 4) ? i : (60 + i));
#pragma unroll
        for (int jh = 0; jh < 2; jh++) {
            int gc = bn + c0 + jh * 64;
            float4 bb = *(const float4*)&bias[gc];
            float4 v;
            v.x = acc[i][jh * 4 + 0] + bb.x;
            v.y = acc[i][jh * 4 + 1] + bb.y;
            v.z = acc[i][jh * 4 + 2] + bb.z;
            v.w = acc[i][jh * 4 + 3] + bb.w;
            if (omode < 3) {
                int b = gr >> 11, srow = gr & (SS - 1);
                int h = gc >> 6, d = gc & (DH - 1);
                *(float4*)&out[(((size_t)b * HH + h) * SS + srow) * DH + d] = v;
            } else {
                *(float4*)&out[(size_t)gr * N + gc] = v;
            }
        }
    }
}

// ---------------------------------------------------------------------------
// Flash attention: one CTA = 64 queries of one (b,h); streams KV in 64-chunks.
// 256 threads, 4x4 fragments. Score cols strided by 16 (conflict-min K reads);
// O cols contiguous (conflict-min V reads). Online softmax in registers.
// ---------------------------------------------------------------------------
__global__ __launch_bounds__(256) void attn_kernel()
{
    extern __shared__ float sm[];
    float* Qs = sm;                    // [64][64]
    float* Ks = sm + 64 * 64;          // [64][68]
    float* Vs = Ks + 64 * 68;          // [64][68]
    float* Ps = Vs + 64 * 68;          // [64][68]

    const int qb = blockIdx.x;         // 0..31
    const int bh = blockIdx.y;         // 0..63
    const float* Qg = g_Q + (size_t)bh * SS * DH + (size_t)qb * 64 * DH;
    const float* Kg = g_K + (size_t)bh * SS * DH;
    const float* Vg = g_V + (size_t)bh * SS * DH;

    const int tid = threadIdx.x;
    const int tr = (tid >> 4) * 4;     // 4 query rows
    const int tc = tid & 15;           // col lane

    // Load + pre-scale Q
#pragma unroll
    for (int t = 0; t < 4; t++) {
        int f4 = tid + t * 256;        // 0..1023
        int row = f4 >> 4, c4 = f4 & 15;
        float4 v = *(const float4*)&Qg[(size_t)row * DH + c4 * 4];
        v.x *= SCALE_F; v.y *= SCALE_F; v.z *= SCALE_F; v.w *= SCALE_F;
        *(float4*)&Qs[row * 64 + c4 * 4] = v;
    }

    float m_i[4], l_i[4], acc[4][4];
#pragma unroll
    for (int i = 0; i < 4; i++) {
        m_i[i] = -1e30f; l_i[i] = 0.f;
#pragma unroll
        for (int j = 0; j < 4; j++) acc[i][j] = 0.f;
    }

    for (int kv0 = 0; kv0 < SS; kv0 += 64) {
        __syncthreads();  // prior iteration done with Ks/Vs/Ps (also covers Q load)
#pragma unroll
        for (int t = 0; t < 4; t++) {
            int f4 = tid + t * 256;
            int row = f4 >> 4, c4 = f4 & 15;
            *(float4*)&Ks[row * 68 + c4 * 4] =
                *(const float4*)&Kg[(size_t)(kv0 + row) * DH + c4 * 4];
            *(float4*)&Vs[row * 68 + c4 * 4] =
                *(const float4*)&Vg[(size_t)(kv0 + row) * DH + c4 * 4];
        }
        __syncthreads();

        // S = Q * K^T  (thread cols: tc + 16j)
        float s[4][4];
#pragma unroll
        for (int i = 0; i < 4; i++)
#pragma unroll
            for (int j = 0; j < 4; j++) s[i][j] = 0.f;

#pragma unroll
        for (int d0 = 0; d0 < 64; d0 += 4) {
            float qa[4][4], kb[4][4];
#pragma unroll
            for (int i = 0; i < 4; i++)
                *(float4*)qa[i] = *(float4*)&Qs[(tr + i) * 64 + d0];
#pragma unroll
            for (int j = 0; j < 4; j++)
                *(float4*)kb[j] = *(float4*)&Ks[(tc + 16 * j) * 68 + d0];
#pragma unroll
            for (int i = 0; i < 4; i++)
#pragma unroll
                for (int j = 0; j < 4; j++)
                    s[i][j] += qa[i][0] * kb[j][0] + qa[i][1] * kb[j][1]
                             + qa[i][2] * kb[j][2] + qa[i][3] * kb[j][3];
        }

        // Online softmax update (row reductions across the 16 tc lanes)
#pragma unroll
        for (int i = 0; i < 4; i++) {
            float mx = fmaxf(fmaxf(s[i][0], s[i][1]), fmaxf(s[i][2], s[i][3]));
            mx = fmaxf(mx, __shfl_xor_sync(0xffffffffu, mx, 1));
            mx = fmaxf(mx, __shfl_xor_sync(0xffffffffu, mx, 2));
            mx = fmaxf(mx, __shfl_xor_sync(0xffffffffu, mx, 4));
            mx = fmaxf(mx, __shfl_xor_sync(0xffffffffu, mx, 8));
            float mnew = fmaxf(m_i[i], mx);
            float corr = __expf(m_i[i] - mnew);
            m_i[i] = mnew;
            float rs = 0.f;
#pragma unroll
            for (int j = 0; j < 4; j++) {
                float p = __expf(s[i][j] - mnew);
                Ps[(tr + i) * 68 + tc + 16 * j] = p;
                rs += p;
            }
            rs += __shfl_xor_sync(0xffffffffu, rs, 1);
            rs += __shfl_xor_sync(0xffffffffu, rs, 2);
            rs += __shfl_xor_sync(0xffffffffu, rs, 4);
            rs += __shfl_xor_sync(0xffffffffu, rs, 8);
            l_i[i] = l_i[i] * corr + rs;
#pragma unroll
            for (int j = 0; j < 4; j++) acc[i][j] *= corr;
        }
        __syncthreads();  // Ps complete

        // O += P * V  (thread cols contiguous: 4*tc..+3)
#pragma unroll
        for (int k0 = 0; k0 < 64; k0 += 4) {
            float pa[4][4];
#pragma unroll
            for (int i = 0; i < 4; i++)
                *(float4*)pa[i] = *(float4*)&Ps[(tr + i) * 68 + k0];
#pragma unroll
            for (int kk = 0; kk < 4; kk++) {
                float4 vb = *(float4*)&Vs[(k0 + kk) * 68 + tc * 4];
#pragma unroll
                for (int i = 0; i < 4; i++) {
                    acc[i][0] += pa[i][kk] * vb.x;
                    acc[i][1] += pa[i][kk] * vb.y;
                    acc[i][2] += pa[i][kk] * vb.z;
                    acc[i][3] += pa[i][kk] * vb.w;
                }
            }
        }
    }

    // Epilogue: normalize, write g_O as [B,S,D]
    const int b = bh >> 4, h = bh & 15;
#pragma unroll
    for (int i = 0; i < 4; i++) {
        float inv = 1.f / l_i[i];
        int srow = qb * 64 + tr + i;
        float4 v;
        v.x = acc[i][0] * inv; v.y = acc[i][1] * inv;
        v.z = acc[i][2] * inv; v.w = acc[i][3] * inv;
        *(float4*)&g_O[((size_t)b * SS + srow) * DD + h * DH + tc * 4] = v;
    }
}

// ---------------------------------------------------------------------------
extern "C" void kernel_launch(void* const* d_in, const int* in_sizes, int n_in,
                              void* d_out, int out_size)
{
    const float* x  = (const float*)d_in[0];
    const float* Wq = (const float*)d_in[1];
    const float* bq = (const float*)d_in[2];
    const float* Wk = (const float*)d_in[3];
    const float* bk = (const float*)d_in[4];
    const float* Wv = (const float*)d_in[5];
    const float* bv = (const float*)d_in[6];
    const float* Wo = (const float*)d_in[7];
    const float* bo = (const float*)d_in[8];
    float* out = (float*)d_out;

    dim3 gg(DD / 128, NT / 128);  // (8, 64)

    gemm128<<<gg, 256>>>(x, Wq, bq, nullptr, 0, 0);
    gemm128<<<gg, 256>>>(x, Wk, bk, nullptr, 0, 1);
    gemm128<<<gg, 256>>>(x, Wv, bv, nullptr, 0, 2);

    const int smem_attn = (64 * 64 + 3 * 64 * 68) * sizeof(float);  // 68608 B
    cudaFuncSetAttribute(attn_kernel, cudaFuncAttributeMaxDynamicSharedMemorySize,
                         smem_attn);
    attn_kernel<<<dim3(SS / 64, BB * HH), 256, smem_attn>>>();

    gemm128<<<gg, 256>>>(nullptr, Wo, bo, out, 1, 3);
}

// round 2
// speedup vs baseline: 3.0142x; 3.0142x over previous
#include <cuda_runtime.h>
#include <math.h>

// Problem constants
#define BB 4
#define SS 2048
#define DD 1024
#define HH 16
#define DH 64
#define NT (BB*SS)          // 8192 tokens
#define SCALE_F 0.125f      // 64^-0.5

// Scratch (device globals: allocation-free rule)
__device__ float g_Q[(size_t)BB*HH*SS*DH];   // [B,H,S,Dh]
__device__ float g_K[(size_t)BB*HH*SS*DH];
__device__ float g_V[(size_t)BB*HH*SS*DH];
__device__ float g_O[(size_t)NT*DD];         // [B,S,D]

// ---------------------------------------------------------------------------
// TF32 helpers
// ---------------------------------------------------------------------------
__device__ __forceinline__ unsigned f2tf(float x) {
    unsigned u;
    asm("cvt.rna.tf32.f32 %0, %1;" : "=r"(u) : "f"(x));
    return u;
}

__device__ __forceinline__ void mma_tf32(float* c, const unsigned* a, const unsigned* b) {
    asm volatile(
        "mma.sync.aligned.m16n8k8.row.col.f32.tf32.tf32.f32 "
        "{%0,%1,%2,%3}, {%4,%5,%6,%7}, {%8,%9}, {%0,%1,%2,%3};\n"
        : "+f"(c[0]), "+f"(c[1]), "+f"(c[2]), "+f"(c[3])
        : "r"(a[0]), "r"(a[1]), "r"(a[2]), "r"(a[3]),
          "r"(b[0]), "r"(b[1]));
}

// ---------------------------------------------------------------------------
// TF32 GEMM: 128x128x32 tiles, 256 threads (8 warps, warp tile 32x64),
// double-buffered smem with register staging.
// amode: 0 -> A = Aparam, 1 -> A = g_O
// omode: 0/1/2 -> write [B,H,S,Dh] into g_Q/g_K/g_V ; 3 -> plain [M,N] to outp
// ---------------------------------------------------------------------------
#define G_ASTR 36
#define G_BSTR 136
#define G_ASZ (128*G_ASTR)
#define G_BSZ (32*G_BSTR)
#define G_SMEM ((2*G_ASZ + 2*G_BSZ)*4)   // 71680 bytes

__global__ __launch_bounds__(256) void gemm_tf32(
    const float* __restrict__ Aparam, const float* __restrict__ W,
    const float* __restrict__ bias, float* __restrict__ outp,
    int amode, int omode)
{
    const int K = DD, N = DD;
    const float* A = amode ? g_O : Aparam;
    float* out = (omode == 0) ? g_Q : (omode == 1) ? g_K : (omode == 2) ? g_V : outp;

    extern __shared__ unsigned smem_u[];
    unsigned* As = smem_u;              // [2][128][36]
    unsigned* Bs = smem_u + 2 * G_ASZ;  // [2][32][136]

    const int bm = blockIdx.y * 128;
    const int bn = blockIdx.x * 128;
    const int tid = threadIdx.x;
    const int warp = tid >> 5, lane = tid & 31;
    const int g = lane >> 2, t = lane & 3;
    const int wm0 = (warp >> 1) * 32;
    const int wn0 = (warp & 1) * 64;

    // gmem load mapping (4 float4 each for A and B tiles)
    const int arow[4] = { (tid + 0) >> 3, (tid + 256) >> 3, (tid + 512) >> 3, (tid + 768) >> 3 };
    const int acol4 = tid & 7;
    const int brow[4] = { (tid + 0) >> 5, (tid + 256) >> 5, (tid + 512) >> 5, (tid + 768) >> 5 };
    const int bcol4 = tid & 31;

    float acc[2][8][4];
#pragma unroll
    for (int mi = 0; mi < 2; mi++)
#pragma unroll
        for (int ni = 0; ni < 8; ni++)
#pragma unroll
            for (int q = 0; q < 4; q++) acc[mi][ni][q] = 0.f;

    uint4 rA[4], rB[4];

    // prologue: load tile 0
#pragma unroll
    for (int p = 0; p < 4; p++) {
        float4 va = *(const float4*)&A[(size_t)(bm + arow[p]) * K + acol4 * 4];
        rA[p] = make_uint4(f2tf(va.x), f2tf(va.y), f2tf(va.z), f2tf(va.w));
        float4 vb = *(const float4*)&W[(size_t)brow[p] * N + bn + bcol4 * 4];
        rB[p] = make_uint4(f2tf(vb.x), f2tf(vb.y), f2tf(vb.z), f2tf(vb.w));
    }
#pragma unroll
    for (int p = 0; p < 4; p++) {
        *(uint4*)&As[arow[p] * G_ASTR + acol4 * 4] = rA[p];
        *(uint4*)&Bs[brow[p] * G_BSTR + bcol4 * 4] = rB[p];
    }
    __syncthreads();

    int buf = 0;
    const int NKT = K / 32;
    for (int kt = 0; kt < NKT; kt++) {
        if (kt + 1 < NKT) {
            const int k0g = (kt + 1) * 32;
#pragma unroll
            for (int p = 0; p < 4; p++) {
                float4 va = *(const float4*)&A[(size_t)(bm + arow[p]) * K + k0g + acol4 * 4];
                rA[p] = make_uint4(f2tf(va.x), f2tf(va.y), f2tf(va.z), f2tf(va.w));
                float4 vb = *(const float4*)&W[(size_t)(k0g + brow[p]) * N + bn + bcol4 * 4];
                rB[p] = make_uint4(f2tf(vb.x), f2tf(vb.y), f2tf(vb.z), f2tf(vb.w));
            }
        }

        const unsigned* Ab = As + buf * G_ASZ;
        const unsigned* Bb = Bs + buf * G_BSZ;
#pragma unroll
        for (int ks = 0; ks < 4; ks++) {
            const int k0 = ks * 8;
            unsigned a[2][4];
#pragma unroll
            for (int mi = 0; mi < 2; mi++) {
                const unsigned* ap = Ab + (wm0 + 16 * mi + g) * G_ASTR;
                a[mi][0] = ap[k0 + t];
                a[mi][2] = ap[k0 + t + 4];
                a[mi][1] = ap[8 * G_ASTR + k0 + t];
                a[mi][3] = ap[8 * G_ASTR + k0 + t + 4];
            }
            unsigned b[8][2];
#pragma unroll
            for (int ni = 0; ni < 8; ni++) {
                b[ni][0] = Bb[(k0 + t) * G_BSTR + wn0 + 8 * ni + g];
                b[ni][1] = Bb[(k0 + t + 4) * G_BSTR + wn0 + 8 * ni + g];
            }
#pragma unroll
            for (int mi = 0; mi < 2; mi++)
#pragma unroll
                for (int ni = 0; ni < 8; ni++)
                    mma_tf32(acc[mi][ni], a[mi], b[ni]);
        }

        if (kt + 1 < NKT) {
#pragma unroll
            for (int p = 0; p < 4; p++) {
                *(uint4*)&As[(buf ^ 1) * G_ASZ + arow[p] * G_ASTR + acol4 * 4] = rA[p];
                *(uint4*)&Bs[(buf ^ 1) * G_BSZ + brow[p] * G_BSTR + bcol4 * 4] = rB[p];
            }
            __syncthreads();
            buf ^= 1;
        }
    }

    // Epilogue: bias + layout
#pragma unroll
    for (int mi = 0; mi < 2; mi++) {
#pragma unroll
        for (int ni = 0; ni < 8; ni++) {
            const int c = bn + wn0 + 8 * ni + 2 * t;
            const float2 bb = *(const float2*)&bias[c];
#pragma unroll
            for (int hr = 0; hr < 2; hr++) {
                const int r = bm + wm0 + 16 * mi + g + 8 * hr;
                float2 v;
                v.x = acc[mi][ni][2 * hr + 0] + bb.x;
                v.y = acc[mi][ni][2 * hr + 1] + bb.y;
                if (omode < 3) {
                    const int b = r >> 11, srow = r & (SS - 1);
                    const int h = c >> 6, d = c & (DH - 1);
                    *(float2*)&out[(((size_t)b * HH + h) * SS + srow) * DH + d] = v;
                } else {
                    *(float2*)&out[(size_t)r * N + c] = v;
                }
            }
        }
    }
}

// ---------------------------------------------------------------------------
// TF32 flash attention: CTA = 128 queries of one (b,h), 256 threads (8 warps,
// 16 q-rows per warp), KV streamed in 64-row chunks. FA2 fragment softmax,
// P routed through smem (tf32) for the PV mma.
// ---------------------------------------------------------------------------
#define A_QSTR 68
#define A_KSTR 68
#define A_VSTR 72
#define A_PSTR 68
#define A_QSZ (128*A_QSTR)
#define A_KSZ (64*A_KSTR)
#define A_VSZ (64*A_VSTR)
#define A_PSZ (128*A_PSTR)
#define A_SMEM ((A_QSZ + A_KSZ + A_VSZ + A_PSZ)*4)   // 105472 bytes

__global__ __launch_bounds__(256) void attn_tf32()
{
    extern __shared__ unsigned sm_u[];
    unsigned* Qs = sm_u;
    unsigned* Ks = Qs + A_QSZ;
    unsigned* Vs = Ks + A_KSZ;
    unsigned* Ps = Vs + A_VSZ;

    const int qb = blockIdx.x;         // 0..15 (128-query tiles)
    const int bh = blockIdx.y;         // 0..63
    const float* Qg = g_Q + (size_t)bh * SS * DH + (size_t)qb * 128 * DH;
    const float* Kg = g_K + (size_t)bh * SS * DH;
    const float* Vg = g_V + (size_t)bh * SS * DH;

    const int tid = threadIdx.x;
    const int warp = tid >> 5, lane = tid & 31;
    const int g = lane >> 2, t = lane & 3;
    const int m0 = warp * 16;          // warp's 16 query rows

    // Load + scale Q: 128x64 -> 8 float4 per thread
#pragma unroll
    for (int p = 0; p < 8; p++) {
        const int idx = tid + p * 256;
        const int row = idx >> 4, c4 = idx & 15;
        float4 v = *(const float4*)&Qg[(size_t)row * DH + c4 * 4];
        uint4 u = make_uint4(f2tf(v.x * SCALE_F), f2tf(v.y * SCALE_F),
                             f2tf(v.z * SCALE_F), f2tf(v.w * SCALE_F));
        *(uint4*)&Qs[row * A_QSTR + c4 * 4] = u;
    }

    float o[8][4];
#pragma unroll
    for (int ni = 0; ni < 8; ni++)
#pragma unroll
        for (int q = 0; q < 4; q++) o[ni][q] = 0.f;
    float mi0 = -1e30f, mi1 = -1e30f, li0 = 0.f, li1 = 0.f;

    for (int kv0 = 0; kv0 < SS; kv0 += 64) {
        __syncthreads();   // Ks/Vs free (and Q visible on first iter)
        // Load K,V chunk: 64x64 each -> 4 float4 per thread per tensor
#pragma unroll
        for (int p = 0; p < 4; p++) {
            const int idx = tid + p * 256;
            const int row = idx >> 4, c4 = idx & 15;
            float4 vk = *(const float4*)&Kg[(size_t)(kv0 + row) * DH + c4 * 4];
            *(uint4*)&Ks[row * A_KSTR + c4 * 4] =
                make_uint4(f2tf(vk.x), f2tf(vk.y), f2tf(vk.z), f2tf(vk.w));
            float4 vv = *(const float4*)&Vg[(size_t)(kv0 + row) * DH + c4 * 4];
            *(uint4*)&Vs[row * A_VSTR + c4 * 4] =
                make_uint4(f2tf(vv.x), f2tf(vv.y), f2tf(vv.z), f2tf(vv.w));
        }
        __syncthreads();

        // S = Q K^T : warp computes 16x64
        float s[8][4];
#pragma unroll
        for (int ni = 0; ni < 8; ni++)
#pragma unroll
            for (int q = 0; q < 4; q++) s[ni][q] = 0.f;

#pragma unroll
        for (int ks = 0; ks < 8; ks++) {
            const int k0 = ks * 8;
            unsigned a[4];
            const unsigned* qp = Qs + (m0 + g) * A_QSTR;
            a[0] = qp[k0 + t];
            a[2] = qp[k0 + t + 4];
            a[1] = qp[8 * A_QSTR + k0 + t];
            a[3] = qp[8 * A_QSTR + k0 + t + 4];
#pragma unroll
            for (int ni = 0; ni < 8; ni++) {
                unsigned b[2];
                b[0] = Ks[(8 * ni + g) * A_KSTR + k0 + t];
                b[1] = Ks[(8 * ni + g) * A_KSTR + k0 + t + 4];
                mma_tf32(s[ni], a, b);
            }
        }

        // Online softmax on fragments (rows r0 = m0+g, r1 = r0+8)
        float mx0 = -1e30f, mx1 = -1e30f;
#pragma unroll
        for (int ni = 0; ni < 8; ni++) {
            mx0 = fmaxf(mx0, fmaxf(s[ni][0], s[ni][1]));
            mx1 = fmaxf(mx1, fmaxf(s[ni][2], s[ni][3]));
        }
        mx0 = fmaxf(mx0, __shfl_xor_sync(0xffffffffu, mx0, 1));
        mx0 = fmaxf(mx0, __shfl_xor_sync(0xffffffffu, mx0, 2));
        mx1 = fmaxf(mx1, __shfl_xor_sync(0xffffffffu, mx1, 1));
        mx1 = fmaxf(mx1, __shfl_xor_sync(0xffffffffu, mx1, 2));

        const float mn0 = fmaxf(mi0, mx0), mn1 = fmaxf(mi1, mx1);
        const float corr0 = __expf(mi0 - mn0), corr1 = __expf(mi1 - mn1);
        mi0 = mn0; mi1 = mn1;

        float rs0 = 0.f, rs1 = 0.f;
#pragma unroll
        for (int ni = 0; ni < 8; ni++) {
            const float p00 = __expf(s[ni][0] - mn0);
            const float p01 = __expf(s[ni][1] - mn0);
            const float p10 = __expf(s[ni][2] - mn1);
            const float p11 = __expf(s[ni][3] - mn1);
            rs0 += p00 + p01;
            rs1 += p10 + p11;
            *(uint2*)&Ps[(m0 + g) * A_PSTR + 8 * ni + 2 * t] =
                make_uint2(f2tf(p00), f2tf(p01));
            *(uint2*)&Ps[(m0 + 8 + g) * A_PSTR + 8 * ni + 2 * t] =
                make_uint2(f2tf(p10), f2tf(p11));
        }
        rs0 += __shfl_xor_sync(0xffffffffu, rs0, 1);
        rs0 += __shfl_xor_sync(0xffffffffu, rs0, 2);
        rs1 += __shfl_xor_sync(0xffffffffu, rs1, 1);
        rs1 += __shfl_xor_sync(0xffffffffu, rs1, 2);
        li0 = li0 * corr0 + rs0;
        li1 = li1 * corr1 + rs1;
#pragma unroll
        for (int ni = 0; ni < 8; ni++) {
            o[ni][0] *= corr0; o[ni][1] *= corr0;
            o[ni][2] *= corr1; o[ni][3] *= corr1;
        }
        __syncwarp();   // P visible within warp (P rows are warp-private)

        // O += P V : warp 16x64, k over the 64 kv rows
#pragma unroll
        for (int ks = 0; ks < 8; ks++) {
            const int k0 = ks * 8;
            unsigned a[4];
            const unsigned* pp = Ps + (m0 + g) * A_PSTR;
            a[0] = pp[k0 + t];
            a[2] = pp[k0 + t + 4];
            a[1] = pp[8 * A_PSTR + k0 + t];
            a[3] = pp[8 * A_PSTR + k0 + t + 4];
#pragma unroll
            for (int ni = 0; ni < 8; ni++) {
                unsigned b[2];
                b[0] = Vs[(k0 + t) * A_VSTR + 8 * ni + g];
                b[1] = Vs[(k0 + t + 4) * A_VSTR + 8 * ni + g];
                mma_tf32(o[ni], a, b);
            }
        }
    }

    // Epilogue: normalize, write g_O as [B,S,D]
    const int b = bh >> 4, h = bh & 15;
    const float inv0 = 1.f / li0, inv1 = 1.f / li1;
#pragma unroll
    for (int ni = 0; ni < 8; ni++) {
        const int col = h * DH + 8 * ni + 2 * t;
        const int s0 = qb * 128 + m0 + g;
        float2 v0 = make_float2(o[ni][0] * inv0, o[ni][1] * inv0);
        float2 v1 = make_float2(o[ni][2] * inv1, o[ni][3] * inv1);
        *(float2*)&g_O[((size_t)b * SS + s0) * DD + col] = v0;
        *(float2*)&g_O[((size_t)b * SS + s0 + 8) * DD + col] = v1;
    }
}

// ---------------------------------------------------------------------------
extern "C" void kernel_launch(void* const* d_in, const int* in_sizes, int n_in,
                              void* d_out, int out_size)
{
    const float* x  = (const float*)d_in[0];
    const float* Wq = (const float*)d_in[1];
    const float* bq = (const float*)d_in[2];
    const float* Wk = (const float*)d_in[3];
    const float* bk = (const float*)d_in[4];
    const float* Wv = (const float*)d_in[5];
    const float* bv = (const float*)d_in[6];
    const float* Wo = (const float*)d_in[7];
    const float* bo = (const float*)d_in[8];
    float* out = (float*)d_out;

    static int configured = 0;
    if (!configured) {
        cudaFuncSetAttribute(gemm_tf32, cudaFuncAttributeMaxDynamicSharedMemorySize, G_SMEM);
        cudaFuncSetAttribute(attn_tf32, cudaFuncAttributeMaxDynamicSharedMemorySize, A_SMEM);
        configured = 1;
    }

    dim3 gg(DD / 128, NT / 128);  // (8, 64)

    gemm_tf32<<<gg, 256, G_SMEM>>>(x, Wq, bq, nullptr, 0, 0);
    gemm_tf32<<<gg, 256, G_SMEM>>>(x, Wk, bk, nullptr, 0, 1);
    gemm_tf32<<<gg, 256, G_SMEM>>>(x, Wv, bv, nullptr, 0, 2);

    attn_tf32<<<dim3(SS / 128, BB * HH), 256, A_SMEM>>>();

    gemm_tf32<<<gg, 256, G_SMEM>>>(nullptr, Wo, bo, out, 1, 3);
}

// round 3
// speedup vs baseline: 3.3973x; 1.1271x over previous
#include <cuda_runtime.h>
#include <math.h>

// Problem constants
#define BB 4
#define SS 2048
#define DD 1024
#define HH 16
#define DH 64
#define NT (BB*SS)          // 8192 tokens
#define SCALE_F 0.125f      // 64^-0.5

// Scratch (device globals: allocation-free rule)
__device__ float g_Q[(size_t)BB*HH*SS*DH];   // [B,H,S,Dh]
__device__ float g_K[(size_t)BB*HH*SS*DH];
__device__ float g_V[(size_t)BB*HH*SS*DH];
__device__ float g_O[(size_t)NT*DD];         // [B,S,D]

// ---------------------------------------------------------------------------
// TF32 helpers
// ---------------------------------------------------------------------------
__device__ __forceinline__ unsigned f2tf(float x) {
    unsigned u;
    asm("cvt.rna.tf32.f32 %0, %1;" : "=r"(u) : "f"(x));
    return u;
}

__device__ __forceinline__ void mma_tf32(float* c, const unsigned* a, const unsigned* b) {
    asm volatile(
        "mma.sync.aligned.m16n8k8.row.col.f32.tf32.tf32.f32 "
        "{%0,%1,%2,%3}, {%4,%5,%6,%7}, {%8,%9}, {%0,%1,%2,%3};\n"
        : "+f"(c[0]), "+f"(c[1]), "+f"(c[2]), "+f"(c[3])
        : "r"(a[0]), "r"(a[1]), "r"(a[2]), "r"(a[3]),
          "r"(b[0]), "r"(b[1]));
}

__device__ __forceinline__ void cp_async16(unsigned smem_addr, const void* gptr) {
    asm volatile("cp.async.ca.shared.global [%0], [%1], 16;\n"
                 :: "r"(smem_addr), "l"(gptr));
}
__device__ __forceinline__ void cp_commit() {
    asm volatile("cp.async.commit_group;\n" ::: "memory");
}
template<int N>
__device__ __forceinline__ void cp_wait() {
    asm volatile("cp.async.wait_group %0;\n" :: "n"(N) : "memory");
}

// ---------------------------------------------------------------------------
// TF32 GEMM: 128x128x32 tiles, 256 threads (8 warps, warp tile 32x64),
// double-buffered smem with register staging.  (unchanged from round 2)
// ---------------------------------------------------------------------------
#define G_ASTR 36
#define G_BSTR 136
#define G_ASZ (128*G_ASTR)
#define G_BSZ (32*G_BSTR)
#define G_SMEM ((2*G_ASZ + 2*G_BSZ)*4)   // 71680 bytes

__global__ __launch_bounds__(256) void gemm_tf32(
    const float* __restrict__ Aparam, const float* __restrict__ W,
    const float* __restrict__ bias, float* __restrict__ outp,
    int amode, int omode)
{
    const int K = DD, N = DD;
    const float* A = amode ? g_O : Aparam;
    float* out = (omode == 0) ? g_Q : (omode == 1) ? g_K : (omode == 2) ? g_V : outp;

    extern __shared__ unsigned smem_u[];
    unsigned* As = smem_u;              // [2][128][36]
    unsigned* Bs = smem_u + 2 * G_ASZ;  // [2][32][136]

    const int bm = blockIdx.y * 128;
    const int bn = blockIdx.x * 128;
    const int tid = threadIdx.x;
    const int warp = tid >> 5, lane = tid & 31;
    const int g = lane >> 2, t = lane & 3;
    const int wm0 = (warp >> 1) * 32;
    const int wn0 = (warp & 1) * 64;

    const int arow[4] = { (tid + 0) >> 3, (tid + 256) >> 3, (tid + 512) >> 3, (tid + 768) >> 3 };
    const int acol4 = tid & 7;
    const int brow[4] = { (tid + 0) >> 5, (tid + 256) >> 5, (tid + 512) >> 5, (tid + 768) >> 5 };
    const int bcol4 = tid & 31;

    float acc[2][8][4];
#pragma unroll
    for (int mi = 0; mi < 2; mi++)
#pragma unroll
        for (int ni = 0; ni < 8; ni++)
#pragma unroll
            for (int q = 0; q < 4; q++) acc[mi][ni][q] = 0.f;

    uint4 rA[4], rB[4];

#pragma unroll
    for (int p = 0; p < 4; p++) {
        float4 va = *(const float4*)&A[(size_t)(bm + arow[p]) * K + acol4 * 4];
        rA[p] = make_uint4(f2tf(va.x), f2tf(va.y), f2tf(va.z), f2tf(va.w));
        float4 vb = *(const float4*)&W[(size_t)brow[p] * N + bn + bcol4 * 4];
        rB[p] = make_uint4(f2tf(vb.x), f2tf(vb.y), f2tf(vb.z), f2tf(vb.w));
    }
#pragma unroll
    for (int p = 0; p < 4; p++) {
        *(uint4*)&As[arow[p] * G_ASTR + acol4 * 4] = rA[p];
        *(uint4*)&Bs[brow[p] * G_BSTR + bcol4 * 4] = rB[p];
    }
    __syncthreads();

    int buf = 0;
    const int NKT = K / 32;
    for (int kt = 0; kt < NKT; kt++) {
        if (kt + 1 < NKT) {
            const int k0g = (kt + 1) * 32;
#pragma unroll
            for (int p = 0; p < 4; p++) {
                float4 va = *(const float4*)&A[(size_t)(bm + arow[p]) * K + k0g + acol4 * 4];
                rA[p] = make_uint4(f2tf(va.x), f2tf(va.y), f2tf(va.z), f2tf(va.w));
                float4 vb = *(const float4*)&W[(size_t)(k0g + brow[p]) * N + bn + bcol4 * 4];
                rB[p] = make_uint4(f2tf(vb.x), f2tf(vb.y), f2tf(vb.z), f2tf(vb.w));
            }
        }

        const unsigned* Ab = As + buf * G_ASZ;
        const unsigned* Bb = Bs + buf * G_BSZ;
#pragma unroll
        for (int ks = 0; ks < 4; ks++) {
            const int k0 = ks * 8;
            unsigned a[2][4];
#pragma unroll
            for (int mi = 0; mi < 2; mi++) {
                const unsigned* ap = Ab + (wm0 + 16 * mi + g) * G_ASTR;
                a[mi][0] = ap[k0 + t];
                a[mi][2] = ap[k0 + t + 4];
                a[mi][1] = ap[8 * G_ASTR + k0 + t];
                a[mi][3] = ap[8 * G_ASTR + k0 + t + 4];
            }
            unsigned b[8][2];
#pragma unroll
            for (int ni = 0; ni < 8; ni++) {
                b[ni][0] = Bb[(k0 + t) * G_BSTR + wn0 + 8 * ni + g];
                b[ni][1] = Bb[(k0 + t + 4) * G_BSTR + wn0 + 8 * ni + g];
            }
#pragma unroll
            for (int mi = 0; mi < 2; mi++)
#pragma unroll
                for (int ni = 0; ni < 8; ni++)
                    mma_tf32(acc[mi][ni], a[mi], b[ni]);
        }

        if (kt + 1 < NKT) {
#pragma unroll
            for (int p = 0; p < 4; p++) {
                *(uint4*)&As[(buf ^ 1) * G_ASZ + arow[p] * G_ASTR + acol4 * 4] = rA[p];
                *(uint4*)&Bs[(buf ^ 1) * G_BSZ + brow[p] * G_BSTR + bcol4 * 4] = rB[p];
            }
            __syncthreads();
            buf ^= 1;
        }
    }

#pragma unroll
    for (int mi = 0; mi < 2; mi++) {
#pragma unroll
        for (int ni = 0; ni < 8; ni++) {
            const int c = bn + wn0 + 8 * ni + 2 * t;
            const float2 bb = *(const float2*)&bias[c];
#pragma unroll
            for (int hr = 0; hr < 2; hr++) {
                const int r = bm + wm0 + 16 * mi + g + 8 * hr;
                float2 v;
                v.x = acc[mi][ni][2 * hr + 0] + bb.x;
                v.y = acc[mi][ni][2 * hr + 1] + bb.y;
                if (omode < 3) {
                    const int b = r >> 11, srow = r & (SS - 1);
                    const int h = c >> 6, d = c & (DH - 1);
                    *(float2*)&out[(((size_t)b * HH + h) * SS + srow) * DH + d] = v;
                } else {
                    *(float2*)&out[(size_t)r * N + c] = v;
                }
            }
        }
    }
}

// ---------------------------------------------------------------------------
// TF32 flash attention v2:
//  - CTA = 128 queries of one (b,h), 128 threads (4 warps, 32 q-rows each, mi=2)
//  - Q fragments register-resident (staged once through the P buffer)
//  - K/V double-buffered in smem via cp.async (raw f32 bits -> tf32 truncation)
//  - P routed through smem for the PV mma (fragment layout mismatch)
//  - 2 CTAs/SM
// ---------------------------------------------------------------------------
#define A_KSTR 68
#define A_VSTR 72
#define A_PSTR 68
#define A_KSZ (64*A_KSTR)
#define A_VSZ (64*A_VSTR)
#define A_PSZ (128*A_PSTR)
#define A_SMEM ((A_PSZ + 2*A_KSZ + 2*A_VSZ)*4)   // 106496 bytes

__global__ __launch_bounds__(128, 2) void attn_tf32()
{
    extern __shared__ unsigned sm_u[];
    unsigned* Ps = sm_u;                 // [128][68], also Q staging
    unsigned* Ks = Ps + A_PSZ;           // [2][64][68]
    unsigned* Vs = Ks + 2 * A_KSZ;       // [2][64][72]

    const int qb = blockIdx.x;           // 0..15
    const int bh = blockIdx.y;           // 0..63
    const float* Qg = g_Q + (size_t)bh * SS * DH + (size_t)qb * 128 * DH;
    const float* Kg = g_K + (size_t)bh * SS * DH;
    const float* Vg = g_V + (size_t)bh * SS * DH;

    const int tid = threadIdx.x;
    const int warp = tid >> 5, lane = tid & 31;
    const int g = lane >> 2, t = lane & 3;
    const int m0 = warp * 32;            // warp's 32 query rows

    const unsigned ksm_base = (unsigned)__cvta_generic_to_shared(Ks);
    const unsigned vsm_base = (unsigned)__cvta_generic_to_shared(Vs);

    // cp.async mapping for one 64x64 chunk: 1024 16B segs / 128 thr = 8 each
    const int cprow[8] = { (tid+0)>>4, (tid+128)>>4, (tid+256)>>4, (tid+384)>>4,
                           (tid+512)>>4, (tid+640)>>4, (tid+768)>>4, (tid+896)>>4 };
    const int cpc16 = tid & 15;

    // ---- prologue: start chunk 0 load ----
#pragma unroll
    for (int p = 0; p < 8; p++) {
        cp_async16(ksm_base + (cprow[p] * A_KSTR + cpc16 * 4) * 4,
                   &Kg[(size_t)cprow[p] * DH + cpc16 * 4]);
        cp_async16(vsm_base + (cprow[p] * A_VSTR + cpc16 * 4) * 4,
                   &Vg[(size_t)cprow[p] * DH + cpc16 * 4]);
    }
    cp_commit();

    // ---- stage Q through Ps, extract fragments to registers ----
#pragma unroll
    for (int p = 0; p < 16; p++) {
        const int idx = tid + p * 128;
        const int row = idx >> 4, c4 = idx & 15;
        float4 v = *(const float4*)&Qg[(size_t)row * DH + c4 * 4];
        *(uint4*)&Ps[row * A_PSTR + c4 * 4] =
            make_uint4(f2tf(v.x * SCALE_F), f2tf(v.y * SCALE_F),
                       f2tf(v.z * SCALE_F), f2tf(v.w * SCALE_F));
    }
    __syncthreads();

    unsigned qf[2][8][4];
#pragma unroll
    for (int mi = 0; mi < 2; mi++) {
        const unsigned* qp = Ps + (m0 + 16 * mi + g) * A_PSTR;
#pragma unroll
        for (int ks = 0; ks < 8; ks++) {
            const int k0 = ks * 8;
            qf[mi][ks][0] = qp[k0 + t];
            qf[mi][ks][1] = qp[8 * A_PSTR + k0 + t];
            qf[mi][ks][2] = qp[k0 + t + 4];
            qf[mi][ks][3] = qp[8 * A_PSTR + k0 + t + 4];
        }
    }
    // After this, Ps rows are only touched warp-locally (P = warp's own rows).

    float o[2][8][4];
#pragma unroll
    for (int mi = 0; mi < 2; mi++)
#pragma unroll
        for (int ni = 0; ni < 8; ni++)
#pragma unroll
            for (int q = 0; q < 4; q++) o[mi][ni][q] = 0.f;
    float mrow[2][2], lrow[2][2];
#pragma unroll
    for (int mi = 0; mi < 2; mi++) {
        mrow[mi][0] = mrow[mi][1] = -1e30f;
        lrow[mi][0] = lrow[mi][1] = 0.f;
    }

    const int NCH = SS / 64;  // 32
    for (int kt = 0; kt < NCH; kt++) {
        const int buf = kt & 1;
        // prefetch chunk kt+1 into buf^1
        if (kt + 1 < NCH) {
            const int kv1 = (kt + 1) * 64;
            const unsigned kb = ksm_base + (buf ^ 1) * A_KSZ * 4;
            const unsigned vb = vsm_base + (buf ^ 1) * A_VSZ * 4;
#pragma unroll
            for (int p = 0; p < 8; p++) {
                cp_async16(kb + (cprow[p] * A_KSTR + cpc16 * 4) * 4,
                           &Kg[(size_t)(kv1 + cprow[p]) * DH + cpc16 * 4]);
                cp_async16(vb + (cprow[p] * A_VSTR + cpc16 * 4) * 4,
                           &Vg[(size_t)(kv1 + cprow[p]) * DH + cpc16 * 4]);
            }
            cp_commit();
            cp_wait<1>();
        } else {
            cp_wait<0>();
        }
        __syncthreads();   // chunk kt data visible to all warps

        const unsigned* Kb = Ks + buf * A_KSZ;
        const unsigned* Vb = Vs + buf * A_VSZ;

        // ---- S = Q K^T : warp computes 32x64 ----
        float s[2][8][4];
#pragma unroll
        for (int mi = 0; mi < 2; mi++)
#pragma unroll
            for (int ni = 0; ni < 8; ni++)
#pragma unroll
                for (int q = 0; q < 4; q++) s[mi][ni][q] = 0.f;

#pragma unroll
        for (int ks = 0; ks < 8; ks++) {
            const int k0 = ks * 8;
#pragma unroll
            for (int ni = 0; ni < 8; ni++) {
                unsigned b[2];
                b[0] = Kb[(8 * ni + g) * A_KSTR + k0 + t];
                b[1] = Kb[(8 * ni + g) * A_KSTR + k0 + t + 4];
                mma_tf32(s[0][ni], qf[0][ks], b);
                mma_tf32(s[1][ni], qf[1][ks], b);
            }
        }

        // ---- online softmax on fragments ----
#pragma unroll
        for (int mi = 0; mi < 2; mi++) {
            float mx0 = -1e30f, mx1 = -1e30f;
#pragma unroll
            for (int ni = 0; ni < 8; ni++) {
                mx0 = fmaxf(mx0, fmaxf(s[mi][ni][0], s[mi][ni][1]));
                mx1 = fmaxf(mx1, fmaxf(s[mi][ni][2], s[mi][ni][3]));
            }
            mx0 = fmaxf(mx0, __shfl_xor_sync(0xffffffffu, mx0, 1));
            mx0 = fmaxf(mx0, __shfl_xor_sync(0xffffffffu, mx0, 2));
            mx1 = fmaxf(mx1, __shfl_xor_sync(0xffffffffu, mx1, 1));
            mx1 = fmaxf(mx1, __shfl_xor_sync(0xffffffffu, mx1, 2));

            const float mn0 = fmaxf(mrow[mi][0], mx0);
            const float mn1 = fmaxf(mrow[mi][1], mx1);
            const float corr0 = __expf(mrow[mi][0] - mn0);
            const float corr1 = __expf(mrow[mi][1] - mn1);
            mrow[mi][0] = mn0; mrow[mi][1] = mn1;

            float rs0 = 0.f, rs1 = 0.f;
            unsigned* pr0 = Ps + (m0 + 16 * mi + g) * A_PSTR;
            unsigned* pr1 = pr0 + 8 * A_PSTR;
#pragma unroll
            for (int ni = 0; ni < 8; ni++) {
                const float p00 = __expf(s[mi][ni][0] - mn0);
                const float p01 = __expf(s[mi][ni][1] - mn0);
                const float p10 = __expf(s[mi][ni][2] - mn1);
                const float p11 = __expf(s[mi][ni][3] - mn1);
                rs0 += p00 + p01;
                rs1 += p10 + p11;
                *(uint2*)&pr0[8 * ni + 2 * t] = make_uint2(f2tf(p00), f2tf(p01));
                *(uint2*)&pr1[8 * ni + 2 * t] = make_uint2(f2tf(p10), f2tf(p11));
            }
            rs0 += __shfl_xor_sync(0xffffffffu, rs0, 1);
            rs0 += __shfl_xor_sync(0xffffffffu, rs0, 2);
            rs1 += __shfl_xor_sync(0xffffffffu, rs1, 1);
            rs1 += __shfl_xor_sync(0xffffffffu, rs1, 2);
            lrow[mi][0] = lrow[mi][0] * corr0 + rs0;
            lrow[mi][1] = lrow[mi][1] * corr1 + rs1;
#pragma unroll
            for (int ni = 0; ni < 8; ni++) {
                o[mi][ni][0] *= corr0; o[mi][ni][1] *= corr0;
                o[mi][ni][2] *= corr1; o[mi][ni][3] *= corr1;
            }
        }
        __syncwarp();   // P rows are warp-private

        // ---- O += P V : warp 32x64, k over 64 kv rows ----
#pragma unroll
        for (int ks = 0; ks < 8; ks++) {
            const int k0 = ks * 8;
            unsigned a[2][4];
#pragma unroll
            for (int mi = 0; mi < 2; mi++) {
                const unsigned* pp = Ps + (m0 + 16 * mi + g) * A_PSTR;
                a[mi][0] = pp[k0 + t];
                a[mi][1] = pp[8 * A_PSTR + k0 + t];
                a[mi][2] = pp[k0 + t + 4];
                a[mi][3] = pp[8 * A_PSTR + k0 + t + 4];
            }
#pragma unroll
            for (int ni = 0; ni < 8; ni++) {
                unsigned b[2];
                b[0] = Vb[(k0 + t) * A_VSTR + 8 * ni + g];
                b[1] = Vb[(k0 + t + 4) * A_VSTR + 8 * ni + g];
                mma_tf32(o[0][ni], a[0], b);
                mma_tf32(o[1][ni], a[1], b);
            }
        }
        __syncthreads();   // all warps done with buf before it is refilled
    }

    // ---- epilogue: normalize, write g_O as [B,S,D] ----
    const int b = bh >> 4, h = bh & 15;
#pragma unroll
    for (int mi = 0; mi < 2; mi++) {
        const float inv0 = 1.f / lrow[mi][0];
        const float inv1 = 1.f / lrow[mi][1];
        const int s0 = qb * 128 + m0 + 16 * mi + g;
#pragma unroll
        for (int ni = 0; ni < 8; ni++) {
            const int col = h * DH + 8 * ni + 2 * t;
            *(float2*)&g_O[((size_t)b * SS + s0) * DD + col] =
                make_float2(o[mi][ni][0] * inv0, o[mi][ni][1] * inv0);
            *(float2*)&g_O[((size_t)b * SS + s0 + 8) * DD + col] =
                make_float2(o[mi][ni][2] * inv1, o[mi][ni][3] * inv1);
        }
    }
}

// ---------------------------------------------------------------------------
extern "C" void kernel_launch(void* const* d_in, const int* in_sizes, int n_in,
                              void* d_out, int out_size)
{
    const float* x  = (const float*)d_in[0];
    const float* Wq = (const float*)d_in[1];
    const float* bq = (const float*)d_in[2];
    const float* Wk = (const float*)d_in[3];
    const float* bk = (const float*)d_in[4];
    const float* Wv = (const float*)d_in[5];
    const float* bv = (const float*)d_in[6];
    const float* Wo = (const float*)d_in[7];
    const float* bo = (const float*)d_in[8];
    float* out = (float*)d_out;

    static int configured = 0;
    if (!configured) {
        cudaFuncSetAttribute(gemm_tf32, cudaFuncAttributeMaxDynamicSharedMemorySize, G_SMEM);
        cudaFuncSetAttribute(attn_tf32, cudaFuncAttributeMaxDynamicSharedMemorySize, A_SMEM);
        configured = 1;
    }

    dim3 gg(DD / 128, NT / 128);  // (8, 64)

    gemm_tf32<<<gg, 256, G_SMEM>>>(x, Wq, bq, nullptr, 0, 0);
    gemm_tf32<<<gg, 256, G_SMEM>>>(x, Wk, bk, nullptr, 0, 1);
    gemm_tf32<<<gg, 256, G_SMEM>>>(x, Wv, bv, nullptr, 0, 2);

    attn_tf32<<<dim3(SS / 128, BB * HH), 128, A_SMEM>>>();

    gemm_tf32<<<gg, 256, G_SMEM>>>(nullptr, Wo, bo, out, 1, 3);
}